// round 8
// baseline (speedup 1.0000x reference)
#include <cuda_runtime.h>

#define NB 64
#define NL 512
#define TILES 8
#define ROWS (NL / TILES)      // 64 i-rows per block
#define NTHREADS 256
#define NBLOCKS (NB * TILES)   // 512
#define RAWF4 (NL * 9 / 4)     // 1152 float4 per batch tensor

__device__ float g_sqrtsum[NBLOCKS];       // per-tile full-matrix sum of sqrt(s1*s2)
__device__ float g_closed[NB];             // per-batch closed-form sum of (s1+s2)
__device__ float g_res[NB];                // per-batch normalized result
__device__ unsigned int g_cnt_batch[NB];   // zero-init; reset each replay
__device__ unsigned int g_cnt_final;       // zero-init; reset each replay

__device__ __forceinline__ float sqrt_approx(float x) {
    float r; asm("sqrt.approx.f32 %0, %1;" : "=f"(r) : "f"(x)); return r;
}

// Full i!=j matrix == 2 * triangle (diagonal ~0).  Per pair (Gram form):
//   err = s1 + s2 - 2*sqrt(s1*s2),  s = n_i + n_j - 2 <x_i, x_j>
// Closed form (exact, O(L)): sum_{i,j}(s1+s2) = 2L*Sum(n) - 2|Sum(x)|^2 per field.
// => 2*sumsq_tri = closed - 2 * sum_full sqrt(s1*s2).
__global__ void __launch_bounds__(NTHREADS) fused_kernel(
    const float* __restrict__ inp, const float* __restrict__ tgt,
    float* __restrict__ out)
{
    __shared__ float4 raw4[RAWF4];     // 18KB coalesced staging buffer (reused)
    __shared__ float4 sIn[NL];         // {x,y,z,|x|^2} input CA
    __shared__ float4 sTg[NL];         // {x,y,z,|x|^2} target CA
    __shared__ float swarp[NTHREADS / 32];
    __shared__ float sred[8][8];

    const int b   = blockIdx.x / TILES;
    const int t   = blockIdx.x % TILES;
    const int tid = threadIdx.x;
    const float* raw = (const float*)raw4;

    // ---- coalesced staging: input ----
    {
        const float4* src = (const float4*)(inp + (size_t)b * NL * 9);
        for (int idx = tid; idx < RAWF4; idx += NTHREADS) raw4[idx] = src[idx];
    }
    __syncthreads();
    for (int k = tid; k < NL; k += NTHREADS) {
        float x = raw[9 * k + 3], y = raw[9 * k + 4], z = raw[9 * k + 5];
        sIn[k] = make_float4(x, y, z, fmaf(x, x, fmaf(y, y, z * z)));
    }
    __syncthreads();
    // ---- coalesced staging: target (reuse raw) ----
    {
        const float4* src = (const float4*)(tgt + (size_t)b * NL * 9);
        for (int idx = tid; idx < RAWF4; idx += NTHREADS) raw4[idx] = src[idx];
    }
    __syncthreads();
    for (int k = tid; k < NL; k += NTHREADS) {
        float x = raw[9 * k + 3], y = raw[9 * k + 4], z = raw[9 * k + 5];
        sTg[k] = make_float4(x, y, z, fmaf(x, x, fmaf(y, y, z * z)));
    }
    __syncthreads();

    // ---- batch stats (tile-0 block only): Sum(x), Sum(n) -> closed form
    if (t == 0) {
        float4 pI, pT;
        {
            float4 a = sIn[tid], b2 = sIn[tid + NTHREADS];
            pI = make_float4(a.x + b2.x, a.y + b2.y, a.z + b2.z, a.w + b2.w);
            float4 c = sTg[tid], d = sTg[tid + NTHREADS];
            pT = make_float4(c.x + d.x, c.y + d.y, c.z + d.z, c.w + d.w);
        }
        for (int off = 16; off > 0; off >>= 1) {
            pI.x += __shfl_down_sync(0xFFFFFFFFu, pI.x, off);
            pI.y += __shfl_down_sync(0xFFFFFFFFu, pI.y, off);
            pI.z += __shfl_down_sync(0xFFFFFFFFu, pI.z, off);
            pI.w += __shfl_down_sync(0xFFFFFFFFu, pI.w, off);
            pT.x += __shfl_down_sync(0xFFFFFFFFu, pT.x, off);
            pT.y += __shfl_down_sync(0xFFFFFFFFu, pT.y, off);
            pT.z += __shfl_down_sync(0xFFFFFFFFu, pT.z, off);
            pT.w += __shfl_down_sync(0xFFFFFFFFu, pT.w, off);
        }
        if ((tid & 31) == 0) {
            int w = tid >> 5;
            sred[w][0] = pI.x; sred[w][1] = pI.y; sred[w][2] = pI.z; sred[w][3] = pI.w;
            sred[w][4] = pT.x; sred[w][5] = pT.y; sred[w][6] = pT.z; sred[w][7] = pT.w;
        }
        __syncthreads();
        if (tid == 0) {
            float v[8];
#pragma unroll
            for (int q = 0; q < 8; ++q) {
                float s = sred[0][q];
#pragma unroll
                for (int w = 1; w < 8; ++w) s += sred[w][q];
                v[q] = s;
            }
            float c1 = 2.0f * NL * v[3] - 2.0f * (v[0]*v[0] + v[1]*v[1] + v[2]*v[2]);
            float c2 = 2.0f * NL * v[7] - 2.0f * (v[4]*v[4] + v[5]*v[5] + v[6]*v[6]);
            g_closed[b] = c1 + c2;
        }
    }

    // ---- each thread owns 2 fixed j-columns: coords prescaled by -2
    const int j0 = tid, j1 = tid + NTHREADS;
    const float4 J0i = sIn[j0], J0t = sTg[j0];
    const float4 J1i = sIn[j1], J1t = sTg[j1];
    const float a0x = -2.f*J0i.x, a0y = -2.f*J0i.y, a0z = -2.f*J0i.z, n0 = J0i.w;
    const float c0x = -2.f*J0t.x, c0y = -2.f*J0t.y, c0z = -2.f*J0t.z, m0 = J0t.w;
    const float a1x = -2.f*J1i.x, a1y = -2.f*J1i.y, a1z = -2.f*J1i.z, n1 = J1i.w;
    const float c1x = -2.f*J1t.x, c1y = -2.f*J1t.y, c1z = -2.f*J1t.z, m1 = J1t.w;

    float acc0 = 0.0f, acc1 = 0.0f;

    const int i0 = t * ROWS;
#pragma unroll 4
    for (int i = i0; i < i0 + ROWS; ++i) {
        const float4 I = sIn[i];   // broadcast LDS.128 (uniform address)
        const float4 T = sTg[i];
        float u0 = fmaf(I.x, a0x, fmaf(I.y, a0y, fmaf(I.z, a0z, I.w)));
        float v0 = fmaf(T.x, c0x, fmaf(T.y, c0y, fmaf(T.z, c0z, T.w)));
        float u1 = fmaf(I.x, a1x, fmaf(I.y, a1y, fmaf(I.z, a1z, I.w)));
        float v1 = fmaf(T.x, c1x, fmaf(T.y, c1y, fmaf(T.z, c1z, T.w)));
        acc0 += sqrt_approx(fmaxf((u0 + n0) * (v0 + m0), 0.0f));
        acc1 += sqrt_approx(fmaxf((u1 + n1) * (v1 + m1), 0.0f));
    }

    float r = acc0 + acc1;

    // ---- block reduce the sqrt-sum
    for (int off = 16; off > 0; off >>= 1)
        r += __shfl_down_sync(0xFFFFFFFFu, r, off);
    if ((tid & 31) == 0) swarp[tid >> 5] = r;
    __syncthreads();
    if (tid < (NTHREADS / 32)) {
        float v = swarp[tid];
        for (int off = (NTHREADS / 64); off > 0; off >>= 1)
            v += __shfl_down_sync(0xFFu, v, off);
        if (tid == 0) g_sqrtsum[blockIdx.x] = v;
    }

    // ---- two-level epilogue: per-batch counter, then final counter ----
    if (tid == 0) {
        __threadfence();
        unsigned int old = atomicAdd(&g_cnt_batch[b], 1u);
        if (old == TILES - 1) {
            // batch-last block: finish this batch (fixed summation order)
            float sq = 0.0f;
#pragma unroll
            for (int k = 0; k < TILES; ++k)
                sq += g_sqrtsum[b * TILES + k];
            float total = g_closed[b] - 2.0f * sq;   // == 2 * sumsq_tri
            float res = sqrtf(total + 1e-6f);
            res *= (1.0f / (sqrtf((float)NL * (float)(NL - 1)) * (float)NL));
            g_res[b] = res;
            g_cnt_batch[b] = 0;                      // reset for next replay
            __threadfence();
            unsigned int o2 = atomicAdd(&g_cnt_final, 1u);
            if (o2 == NB - 1) {
                float s = 0.0f;
#pragma unroll
                for (int bb = 0; bb < NB; ++bb) s += g_res[bb];
                out[0] = s * (1.0f / (float)NB);
                g_cnt_final = 0;                     // reset for next replay
            }
        }
    }
}

extern "C" void kernel_launch(void* const* d_in, const int* in_sizes, int n_in,
                              void* d_out, int out_size)
{
    const float* inp = (const float*)d_in[0];
    const float* tgt = (const float*)d_in[1];
    float* out = (float*)d_out;
    fused_kernel<<<NBLOCKS, NTHREADS>>>(inp, tgt, out);
}

// round 10
// speedup vs baseline: 1.1804x; 1.1804x over previous
#include <cuda_runtime.h>

#define NB 64
#define NL 512
#define NTILE 128              // j/i tile size
#define BPB 10                 // blocks per batch (10 units: 4 diag + 6 rect)
#define NTHREADS 256
#define NBLOCKS (NB * BPB)     // 640
#define GROUPS 4               // 64-thread groups per block
#define ROWS 32                // i-rows per group (128 rows/unit ÷ 4 groups)

__device__ float g_sqrtsum[NBLOCKS];       // per-block weighted sqrt-sum
__device__ float g_closed[NB];             // per-batch closed-form sum of (s1+s2)
__device__ float g_res[NB];                // per-batch normalized result
__device__ unsigned int g_cnt_batch[NB];   // zero-init; reset each replay
__device__ unsigned int g_cnt_final;       // zero-init; reset each replay

__device__ __forceinline__ float sqrt_approx(float x) {
    float r; asm("sqrt.approx.f32 %0, %1;" : "=f"(r) : "f"(x)); return r;
}

// Tiled-triangle enumeration over 4 tiles of 128:
//   units 0..3  = diagonal (t,t): all 128x128 ordered pairs -> each unordered
//                 pair twice, diagonal ~0 -> weight 1/2
//   units 4..9  = rectangles (tj<ti): each unordered cross pair once, weight 1
//   unit->pair map: r = u-4 in 0..5 -> (0,1)(0,2)(0,3)(1,2)(1,3)(2,3)
//     tj = r<3 ? 0 : (r<5 ? 1 : 2);  ti = r<3 ? r+1 : (r<5 ? r-1 : 3)
//   (R9 bug was ti = r-2 for r in {3,4} -> double-counted (1,1), missed (1,3))
// => weighted sum == triangle sqrt-sum; 62.5% of full-matrix pair ops with
//    BROADCAST i-row loads (gather LDS = 4x wavefronts, the R7 lesson).
//
// Per pair (Gram form): err = s1 + s2 - 2*sqrt(s1*s2)
// Closed form (exact): sum_{i,j}(s1+s2) = 2L*Sum(n) - 2|Sum(x)|^2 per field.
// 2*sumsq_tri = closed - 4 * sqrtsum_tri.
__global__ void __launch_bounds__(NTHREADS, 6) fused_kernel(
    const float* __restrict__ inp, const float* __restrict__ tgt,
    float* __restrict__ out)
{
    __shared__ float4 sIn[NL];         // {x,y,z,|x|^2} input CA
    __shared__ float4 sTg[NL];         // {x,y,z,|x|^2} target CA
    __shared__ float swarp[NTHREADS / 32];
    __shared__ float sred[8][8];

    const int b   = blockIdx.x / BPB;
    const int blk = blockIdx.x % BPB;
    const int tid = threadIdx.x;

    // ---- stage CA coords + norms (atom 1 -> floats 3..5 of 9/residue)
    for (int k = tid; k < NL; k += NTHREADS) {
        int base = (b * NL + k) * 9 + 3;
        float ax = inp[base + 0], ay = inp[base + 1], az = inp[base + 2];
        float cx = tgt[base + 0], cy = tgt[base + 1], cz = tgt[base + 2];
        sIn[k] = make_float4(ax, ay, az, fmaf(ax, ax, fmaf(ay, ay, az * az)));
        sTg[k] = make_float4(cx, cy, cz, fmaf(cx, cx, fmaf(cy, cy, cz * cz)));
    }
    __syncthreads();

    // ---- batch stats (block 0 of each batch): Sum(x), Sum(n) -> closed form
    if (blk == 0) {
        float4 pI, pT;
        {
            float4 a = sIn[tid], b2 = sIn[tid + NTHREADS];
            pI = make_float4(a.x + b2.x, a.y + b2.y, a.z + b2.z, a.w + b2.w);
            float4 c = sTg[tid], d = sTg[tid + NTHREADS];
            pT = make_float4(c.x + d.x, c.y + d.y, c.z + d.z, c.w + d.w);
        }
        for (int off = 16; off > 0; off >>= 1) {
            pI.x += __shfl_down_sync(0xFFFFFFFFu, pI.x, off);
            pI.y += __shfl_down_sync(0xFFFFFFFFu, pI.y, off);
            pI.z += __shfl_down_sync(0xFFFFFFFFu, pI.z, off);
            pI.w += __shfl_down_sync(0xFFFFFFFFu, pI.w, off);
            pT.x += __shfl_down_sync(0xFFFFFFFFu, pT.x, off);
            pT.y += __shfl_down_sync(0xFFFFFFFFu, pT.y, off);
            pT.z += __shfl_down_sync(0xFFFFFFFFu, pT.z, off);
            pT.w += __shfl_down_sync(0xFFFFFFFFu, pT.w, off);
        }
        if ((tid & 31) == 0) {
            int w = tid >> 5;
            sred[w][0] = pI.x; sred[w][1] = pI.y; sred[w][2] = pI.z; sred[w][3] = pI.w;
            sred[w][4] = pT.x; sred[w][5] = pT.y; sred[w][6] = pT.z; sred[w][7] = pT.w;
        }
        __syncthreads();
        if (tid == 0) {
            float v[8];
#pragma unroll
            for (int q = 0; q < 8; ++q) {
                float s = sred[0][q];
#pragma unroll
                for (int w = 1; w < 8; ++w) s += sred[w][q];
                v[q] = s;
            }
            float c1 = 2.0f * NL * v[3] - 2.0f * (v[0]*v[0] + v[1]*v[1] + v[2]*v[2]);
            float c2 = 2.0f * NL * v[7] - 2.0f * (v[4]*v[4] + v[5]*v[5] + v[6]*v[6]);
            g_closed[b] = c1 + c2;
        }
    }

    // ---- work assignment: 4 groups of 64 threads; block -> unit, group -> quarter
    const int u    = blk;                         // unit 0..9
    const int q    = tid >> 6;                    // row quarter within unit
    const int ltid = tid & 63;

    int tj, ti;
    if (u < 4) { tj = u; ti = u; }
    else {
        int r = u - 4;                            // (0,1)(0,2)(0,3)(1,2)(1,3)(2,3)
        tj = (r < 3) ? 0 : ((r < 5) ? 1 : 2);
        ti = (r < 3) ? r + 1 : ((r < 5) ? r - 1 : 3);   // FIXED (was r-2)
    }
    const float w = (u < 4) ? 0.5f : 1.0f;

    // ---- j-constants: 2 j's per thread from the j-tile, prescaled by -2
    const int j0 = tj * NTILE + ltid, j1 = j0 + 64;
    const float4 J0i = sIn[j0], J0t = sTg[j0];
    const float4 J1i = sIn[j1], J1t = sTg[j1];
    const float a0x = -2.f*J0i.x, a0y = -2.f*J0i.y, a0z = -2.f*J0i.z, n0 = J0i.w;
    const float c0x = -2.f*J0t.x, c0y = -2.f*J0t.y, c0z = -2.f*J0t.z, m0 = J0t.w;
    const float a1x = -2.f*J1i.x, a1y = -2.f*J1i.y, a1z = -2.f*J1i.z, n1 = J1i.w;
    const float c1x = -2.f*J1t.x, c1y = -2.f*J1t.y, c1z = -2.f*J1t.z, m1 = J1t.w;

    float acc0 = 0.0f, acc1 = 0.0f;

    const int i0 = ti * NTILE + q * ROWS;
#pragma unroll 8
    for (int i = i0; i < i0 + ROWS; ++i) {
        const float4 I = sIn[i];   // broadcast LDS.128
        const float4 T = sTg[i];
        float u0 = fmaf(I.x, a0x, fmaf(I.y, a0y, fmaf(I.z, a0z, I.w)));
        float v0 = fmaf(T.x, c0x, fmaf(T.y, c0y, fmaf(T.z, c0z, T.w)));
        float u1 = fmaf(I.x, a1x, fmaf(I.y, a1y, fmaf(I.z, a1z, I.w)));
        float v1 = fmaf(T.x, c1x, fmaf(T.y, c1y, fmaf(T.z, c1z, T.w)));
        acc0 += sqrt_approx(fmaxf((u0 + n0) * (v0 + m0), 0.0f));
        acc1 += sqrt_approx(fmaxf((u1 + n1) * (v1 + m1), 0.0f));
    }

    float r = (acc0 + acc1) * w;   // diag units weighted 1/2

    // ---- block reduce the weighted sqrt-sum
    for (int off = 16; off > 0; off >>= 1)
        r += __shfl_down_sync(0xFFFFFFFFu, r, off);
    if ((tid & 31) == 0) swarp[tid >> 5] = r;
    __syncthreads();
    if (tid < (NTHREADS / 32)) {
        float v = swarp[tid];
        for (int off = (NTHREADS / 64); off > 0; off >>= 1)
            v += __shfl_down_sync(0xFFu, v, off);
        if (tid == 0) g_sqrtsum[blockIdx.x] = v;
    }

    // ---- two-level epilogue: per-batch counter, then final counter ----
    if (tid == 0) {
        __threadfence();
        unsigned int old = atomicAdd(&g_cnt_batch[b], 1u);
        if (old == BPB - 1) {
            float sq = 0.0f;                      // triangle sqrt-sum (fixed order)
#pragma unroll
            for (int k = 0; k < BPB; ++k)
                sq += g_sqrtsum[b * BPB + k];
            float total = g_closed[b] - 4.0f * sq;   // == 2 * sumsq_tri
            float res = sqrtf(total + 1e-6f);
            res *= (1.0f / (sqrtf((float)NL * (float)(NL - 1)) * (float)NL));
            g_res[b] = res;
            g_cnt_batch[b] = 0;                   // reset for next replay
            __threadfence();
            unsigned int o2 = atomicAdd(&g_cnt_final, 1u);
            if (o2 == NB - 1) {
                float s = 0.0f;
#pragma unroll
                for (int bb = 0; bb < NB; ++bb) s += g_res[bb];
                out[0] = s * (1.0f / (float)NB);
                g_cnt_final = 0;                  // reset for next replay
            }
        }
    }
}

extern "C" void kernel_launch(void* const* d_in, const int* in_sizes, int n_in,
                              void* d_out, int out_size)
{
    const float* inp = (const float*)d_in[0];
    const float* tgt = (const float*)d_in[1];
    float* out = (float*)d_out;
    fused_kernel<<<NBLOCKS, NTHREADS>>>(inp, tgt, out);
}

// round 11
// speedup vs baseline: 1.2472x; 1.0566x over previous
#include <cuda_runtime.h>

#define NB 64
#define NL 512
#define NTILE 128
#define SUB 20                 // sub-units per batch: 10 units x 2 row-halves
#define NTHREADS 128
#define NBLOCKS (NB * SUB)     // 1280

__device__ float g_sqrtsum[NBLOCKS];       // per-block weighted sqrt-sum
__device__ float g_stats[NB * 4 * 8];      // per (batch, tile): Sx,Sy,Sz,Sn (in), same (tg)
__device__ float g_res[NB];
__device__ unsigned int g_cnt_batch[NB];   // zero-init; reset each replay
__device__ unsigned int g_cnt_final;       // zero-init; reset each replay

__device__ __forceinline__ float sqrt_approx(float x) {
    float r; asm("sqrt.approx.f32 %0, %1;" : "=f"(r) : "f"(x)); return r;
}

// Tiled-triangle (4 tiles of 128): diag units (t,t) weight 1/2, rect units
// (tj<ti) weight 1.  Each unit split into 2 i-halves of 64 rows -> 20 blocks
// per batch, all uniform (64 bcast-LDS iterations of 1 pair).
//   rect map r=u-4: (0,1)(0,2)(0,3)(1,2)(1,3)(2,3)
// Per pair (Gram): err = s1 + s2 - 2*sqrt(s1*s2).
// Closed form (per-tile partials, fixed-order combine): sum(s1+s2) =
//   2L*Sum(n) - 2|Sum(x)|^2 per field.   2*sumsq_tri = closed - 4*sqrtsum_tri.
__global__ void __launch_bounds__(NTHREADS) fused_kernel(
    const float* __restrict__ inp, const float* __restrict__ tgt,
    float* __restrict__ out)
{
    __shared__ float4 sJ[NTILE],  sJt[NTILE];   // j-tile {x,y,z,n}
    __shared__ float4 sI[64],     sIt[64];      // i-half (rect only)
    __shared__ float  swarp[4];
    __shared__ float  sst[4][8];

    const int b    = blockIdx.x / SUB;
    const int su   = blockIdx.x % SUB;
    const int u    = su >> 1;          // unit 0..9
    const int half = su & 1;           // i-half
    const int tid  = threadIdx.x;

    int tj, ti;
    if (u < 4) { tj = u; ti = u; }
    else {
        int r = u - 4;
        tj = (r < 3) ? 0 : ((r < 5) ? 1 : 2);
        ti = (r < 3) ? r + 1 : ((r < 5) ? r - 1 : 3);
    }
    const float w = (u < 4) ? 0.5f : 1.0f;

    // ---- targeted staging: j-tile (128 pts), plus i-half (64 pts) for rects
    {
        int p = (b * NL + tj * NTILE + tid) * 9 + 3;
        float ax = inp[p], ay = inp[p + 1], az = inp[p + 2];
        float cx = tgt[p], cy = tgt[p + 1], cz = tgt[p + 2];
        sJ[tid]  = make_float4(ax, ay, az, fmaf(ax, ax, fmaf(ay, ay, az * az)));
        sJt[tid] = make_float4(cx, cy, cz, fmaf(cx, cx, fmaf(cy, cy, cz * cz)));
    }
    if (u >= 4 && tid < 64) {
        int p = (b * NL + ti * NTILE + half * 64 + tid) * 9 + 3;
        float ax = inp[p], ay = inp[p + 1], az = inp[p + 2];
        float cx = tgt[p], cy = tgt[p + 1], cz = tgt[p + 2];
        sI[tid]  = make_float4(ax, ay, az, fmaf(ax, ax, fmaf(ay, ay, az * az)));
        sIt[tid] = make_float4(cx, cy, cz, fmaf(cx, cx, fmaf(cy, cy, cz * cz)));
    }
    __syncthreads();

    // ---- per-tile stats (diag half-0 blocks): sums over this tile's 128 pts
    if (u < 4 && half == 0) {
        float4 a = sJ[tid], c = sJt[tid];
        float v0 = a.x, v1 = a.y, v2 = a.z, v3 = a.w;
        float v4 = c.x, v5 = c.y, v6 = c.z, v7 = c.w;
        for (int off = 16; off > 0; off >>= 1) {
            v0 += __shfl_down_sync(0xFFFFFFFFu, v0, off);
            v1 += __shfl_down_sync(0xFFFFFFFFu, v1, off);
            v2 += __shfl_down_sync(0xFFFFFFFFu, v2, off);
            v3 += __shfl_down_sync(0xFFFFFFFFu, v3, off);
            v4 += __shfl_down_sync(0xFFFFFFFFu, v4, off);
            v5 += __shfl_down_sync(0xFFFFFFFFu, v5, off);
            v6 += __shfl_down_sync(0xFFFFFFFFu, v6, off);
            v7 += __shfl_down_sync(0xFFFFFFFFu, v7, off);
        }
        if ((tid & 31) == 0) {
            int wp = tid >> 5;
            sst[wp][0] = v0; sst[wp][1] = v1; sst[wp][2] = v2; sst[wp][3] = v3;
            sst[wp][4] = v4; sst[wp][5] = v5; sst[wp][6] = v6; sst[wp][7] = v7;
        }
        __syncthreads();
        if (tid == 0) {
#pragma unroll
            for (int q = 0; q < 8; ++q) {
                float s = sst[0][q] + sst[1][q] + sst[2][q] + sst[3][q];
                g_stats[(b * 4 + u) * 8 + q] = s;
            }
        }
    }

    // ---- inner loop: thread owns j = tj*128 + tid, prescaled by -2
    const float4 J = sJ[tid], Jt = sJt[tid];
    const float ax = -2.f * J.x,  ay = -2.f * J.y,  az = -2.f * J.z,  n0 = J.w;
    const float cx = -2.f * Jt.x, cy = -2.f * Jt.y, cz = -2.f * Jt.z, m0 = Jt.w;

    const float4* Ib = (u < 4) ? (sJ  + half * 64) : sI;
    const float4* Tb = (u < 4) ? (sJt + half * 64) : sIt;

    float acc = 0.0f;
#pragma unroll 8
    for (int i = 0; i < 64; ++i) {
        const float4 I = Ib[i];    // broadcast LDS.128
        const float4 T = Tb[i];
        float s1 = fmaf(I.x, ax, fmaf(I.y, ay, fmaf(I.z, az, I.w))) + n0;
        float s2 = fmaf(T.x, cx, fmaf(T.y, cy, fmaf(T.z, cz, T.w))) + m0;
        acc += sqrt_approx(fmaxf(s1 * s2, 0.0f));
    }
    acc *= w;

    // ---- block reduce (4 warps)
    for (int off = 16; off > 0; off >>= 1)
        acc += __shfl_down_sync(0xFFFFFFFFu, acc, off);
    __syncthreads();                       // reuse swarp safely
    if ((tid & 31) == 0) swarp[tid >> 5] = acc;
    __syncthreads();

    // ---- two-level epilogue ----
    if (tid == 0) {
        g_sqrtsum[blockIdx.x] = swarp[0] + swarp[1] + swarp[2] + swarp[3];
        __threadfence();
        unsigned int old = atomicAdd(&g_cnt_batch[b], 1u);
        if (old == SUB - 1) {
            float v[8];
#pragma unroll
            for (int q = 0; q < 8; ++q)        // fixed-order tile combine
                v[q] = g_stats[(b * 4 + 0) * 8 + q] + g_stats[(b * 4 + 1) * 8 + q]
                     + g_stats[(b * 4 + 2) * 8 + q] + g_stats[(b * 4 + 3) * 8 + q];
            float c1 = 2.0f * NL * v[3] - 2.0f * (v[0]*v[0] + v[1]*v[1] + v[2]*v[2]);
            float c2 = 2.0f * NL * v[7] - 2.0f * (v[4]*v[4] + v[5]*v[5] + v[6]*v[6]);
            float sq = 0.0f;                   // fixed-order sqrt-sum
#pragma unroll
            for (int k = 0; k < SUB; ++k)
                sq += g_sqrtsum[b * SUB + k];
            float total = (c1 + c2) - 4.0f * sq;   // == 2 * sumsq_tri
            float res = sqrtf(total + 1e-6f);
            res *= (1.0f / (sqrtf((float)NL * (float)(NL - 1)) * (float)NL));
            g_res[b] = res;
            g_cnt_batch[b] = 0;
            __threadfence();
            unsigned int o2 = atomicAdd(&g_cnt_final, 1u);
            if (o2 == NB - 1) {
                float s = 0.0f;
#pragma unroll
                for (int bb = 0; bb < NB; ++bb) s += g_res[bb];
                out[0] = s * (1.0f / (float)NB);
                g_cnt_final = 0;
            }
        }
    }
}

extern "C" void kernel_launch(void* const* d_in, const int* in_sizes, int n_in,
                              void* d_out, int out_size)
{
    const float* inp = (const float*)d_in[0];
    const float* tgt = (const float*)d_in[1];
    float* out = (float*)d_out;
    fused_kernel<<<NBLOCKS, NTHREADS>>>(inp, tgt, out);
}

// round 12
// speedup vs baseline: 1.2860x; 1.0311x over previous
#include <cuda_runtime.h>

#define NB 64
#define NL 512
#define TS 64                  // tile size
#define NT (NL / TS)           // 8 tiles
#define NUNITS 36              // 8 diag + 28 rect
#define NTHREADS 128
#define NBLOCKS (NB * NUNITS)  // 2304

__device__ float g_sqrtsum[NBLOCKS];        // per-block weighted sqrt-sum
__device__ float g_stats[NB * NT * 8];      // per (batch,tile): Sx,Sy,Sz,Sn (in) + (tg)
__device__ float g_res[NB];
__device__ unsigned int g_cnt_batch[NB];    // zero-init; reset each replay
__device__ unsigned int g_cnt_final;        // zero-init; reset each replay

__device__ __forceinline__ float sqrt_approx(float x) {
    float r; asm("sqrt.approx.f32 %0, %1;" : "=f"(r) : "f"(x)); return r;
}

// 64-wide tiled triangle: diag units (t,t) weight 1/2 (each unordered pair twice,
// diagonal ~0), rect units (tj<ti) weight 1 (each cross pair once).
// Per pair (Gram): err = s1 + s2 - 2*sqrt(s1*s2);  s = n_i + n_j - 2<x_i,x_j>.
// Closed form (per-tile partials, fixed-order combine):
//   sum_{i,j}(s1+s2) = 2L*Sum(n) - 2|Sum(x)|^2 per field.
//   2*sumsq_tri = closed - 4*sqrtsum_tri.
__global__ void __launch_bounds__(NTHREADS) fused_kernel(
    const float* __restrict__ inp, const float* __restrict__ tgt,
    float* __restrict__ out)
{
    __shared__ float4 sJ[TS], sJt[TS];     // j-tile {x,y,z,n}
    __shared__ float4 sI[TS], sIt[TS];     // i-tile (rect only)
    __shared__ float  swarp[4];
    __shared__ float  sst[2][8];

    const int b   = blockIdx.x / NUNITS;
    const int u   = blockIdx.x % NUNITS;
    const int tid = threadIdx.x;

    // unit -> (tj, ti)
    int tj, ti;
    if (u < NT) { tj = u; ti = u; }
    else {
        int rem = u - NT;                  // 0..27 over (tj<ti)
        tj = 0;
        while (rem >= NT - 1 - tj) { rem -= NT - 1 - tj; ++tj; }
        ti = tj + 1 + rem;
    }
    const bool diag = (u < NT);
    const float w = diag ? 0.5f : 1.0f;

    // ---- staging: 1 point-tensor per thread (j-tile), +1 for rect (i-tile)
    {
        int lp  = tid & 63;
        int p   = (b * NL + tj * TS + lp) * 9 + 3;
        const float* src = (tid < 64) ? inp : tgt;
        float x = src[p], y = src[p + 1], z = src[p + 2];
        float4 v = make_float4(x, y, z, fmaf(x, x, fmaf(y, y, z * z)));
        if (tid < 64) sJ[lp] = v; else sJt[lp] = v;
        if (!diag) {
            int p2 = (b * NL + ti * TS + lp) * 9 + 3;
            float x2 = src[p2], y2 = src[p2 + 1], z2 = src[p2 + 2];
            float4 v2 = make_float4(x2, y2, z2, fmaf(x2, x2, fmaf(y2, y2, z2 * z2)));
            if (tid < 64) sI[lp] = v2; else sIt[lp] = v2;
        }
    }
    __syncthreads();

    // ---- per-tile stats (diag blocks): sums over this tile's 64 points
    if (diag) {
        int lp = tid & 63;
        float4 a = (tid < 64) ? sJ[lp] : sJt[lp];
        float v0 = a.x, v1 = a.y, v2 = a.z, v3 = a.w;
        for (int off = 16; off > 0; off >>= 1) {
            v0 += __shfl_down_sync(0xFFFFFFFFu, v0, off);
            v1 += __shfl_down_sync(0xFFFFFFFFu, v1, off);
            v2 += __shfl_down_sync(0xFFFFFFFFu, v2, off);
            v3 += __shfl_down_sync(0xFFFFFFFFu, v3, off);
        }
        if ((tid & 31) == 0) {
            int g = tid >> 6;              // 0 = input, 1 = target
            int hw = (tid >> 5) & 1;       // warp within group
            if (hw == 0) { sst[g][0] = v0; sst[g][1] = v1; sst[g][2] = v2; sst[g][3] = v3; }
            else         { sst[g][4] = v0; sst[g][5] = v1; sst[g][6] = v2; sst[g][7] = v3; }
        }
        __syncthreads();
        if (tid < 8) {
            int g = tid >> 2, q = tid & 3;
            g_stats[(b * NT + u) * 8 + g * 4 + q] = sst[g][q] + sst[g][q + 4];
        }
    }

    // ---- inner loop: thread owns j = tj*64 + (tid&63), i-half by tid>>6
    const int lj = tid & 63;
    const float4 J = sJ[lj], Jt = sJt[lj];
    const float ax = -2.f * J.x,  ay = -2.f * J.y,  az = -2.f * J.z,  n0 = J.w;
    const float cx = -2.f * Jt.x, cy = -2.f * Jt.y, cz = -2.f * Jt.z, m0 = Jt.w;

    const float4* Ib = diag ? sJ  : sI;
    const float4* Tb = diag ? sJt : sIt;
    const int i0 = (tid >> 6) * 32;

    float acc = 0.0f;
#pragma unroll 8
    for (int i = i0; i < i0 + 32; ++i) {
        const float4 I = Ib[i];            // broadcast LDS.128
        const float4 T = Tb[i];
        float s1 = fmaf(I.x, ax, fmaf(I.y, ay, fmaf(I.z, az, I.w))) + n0;
        float s2 = fmaf(T.x, cx, fmaf(T.y, cy, fmaf(T.z, cz, T.w))) + m0;
        acc += sqrt_approx(fmaxf(s1 * s2, 0.0f));
    }
    acc *= w;

    // ---- block reduce (4 warps)
    for (int off = 16; off > 0; off >>= 1)
        acc += __shfl_down_sync(0xFFFFFFFFu, acc, off);
    __syncthreads();
    if ((tid & 31) == 0) swarp[tid >> 5] = acc;
    __syncthreads();

    // ---- two-level epilogue ----
    if (tid == 0) {
        g_sqrtsum[blockIdx.x] = swarp[0] + swarp[1] + swarp[2] + swarp[3];
        __threadfence();
        unsigned int old = atomicAdd(&g_cnt_batch[b], 1u);
        if (old == NUNITS - 1) {
            float v[8];
#pragma unroll
            for (int q = 0; q < 8; ++q) {
                float s = 0.0f;
#pragma unroll
                for (int t = 0; t < NT; ++t)   // fixed-order tile combine
                    s += g_stats[(b * NT + t) * 8 + q];
                v[q] = s;
            }
            float c1 = 2.0f * NL * v[3] - 2.0f * (v[0]*v[0] + v[1]*v[1] + v[2]*v[2]);
            float c2 = 2.0f * NL * v[7] - 2.0f * (v[4]*v[4] + v[5]*v[5] + v[6]*v[6]);
            float sq = 0.0f;                   // fixed-order sqrt-sum
#pragma unroll
            for (int k = 0; k < NUNITS; ++k)
                sq += g_sqrtsum[b * NUNITS + k];
            float total = (c1 + c2) - 4.0f * sq;   // == 2 * sumsq_tri
            float res = sqrtf(total + 1e-6f);
            res *= (1.0f / (sqrtf((float)NL * (float)(NL - 1)) * (float)NL));
            g_res[b] = res;
            g_cnt_batch[b] = 0;
            __threadfence();
            unsigned int o2 = atomicAdd(&g_cnt_final, 1u);
            if (o2 == NB - 1) {
                float s = 0.0f;
#pragma unroll
                for (int bb = 0; bb < NB; ++bb) s += g_res[bb];
                out[0] = s * (1.0f / (float)NB);
                g_cnt_final = 0;
            }
        }
    }
}

extern "C" void kernel_launch(void* const* d_in, const int* in_sizes, int n_in,
                              void* d_out, int out_size)
{
    const float* inp = (const float*)d_in[0];
    const float* tgt = (const float*)d_in[1];
    float* out = (float*)d_out;
    fused_kernel<<<NBLOCKS, NTHREADS>>>(inp, tgt, out);
}